// round 1
// baseline (speedup 1.0000x reference)
#include <cuda_runtime.h>
#include <math.h>

#define NN 50000
#define DD 128
#define EE 625000

// ---------------- scratch (static device allocations; no runtime alloc) ----
__device__ float g_tan_node[NN * DD];        // logmap0(node_embeddings)
__device__ float g_th[NN * 3 * DD];          // packed [n][k*128+i] = logmap0(hist_k)[n,i]
__device__ float g_transformed[NN * DD];     // GEMM1 output
__device__ float g_conv[NN * DD];            // GEMM2 output
__device__ int   g_deg[NN];
__device__ int   g_rowstart[NN + 1];
__device__ int   g_cursor[NN];
__device__ int   g_csr[EE];
__device__ float g_Wt1[DD * DD];             // lin_w packed  [i/4][o][4]
__device__ float g_Wt2[3 * DD * DD];         // conv_w packed [j/4][o][4], j = k*128+i

// ---------------- small utility kernels ------------------------------------
__global__ void zero_deg_kernel() {
    int i = blockIdx.x * blockDim.x + threadIdx.x;
    if (i < NN) g_deg[i] = 0;
}

// Pack weights for conflict-free vectorized smem reads in the GEMMs.
__global__ void prep_weights_kernel(const float* __restrict__ lin_w,
                                    const float* __restrict__ conv_w) {
    int idx = blockIdx.x * blockDim.x + threadIdx.x;
    if (idx < DD * DD) {
        int o = idx >> 7, i = idx & 127;
        g_Wt1[(i >> 2) * (DD * 4) + (o << 2) + (i & 3)] = lin_w[o * DD + i];
    } else {
        int t = idx - DD * DD;            // [0, 3*DD*DD)
        int o = t / (3 * DD);
        int j = t - o * (3 * DD);         // j = k*128 + i
        int k = j >> 7, i = j & 127;
        g_Wt2[(j >> 2) * (DD * 4) + (o << 2) + (j & 3)] =
            conv_w[(o * DD + i) * 3 + k];
    }
}

// ---------------- logmap0 of node + 3 histories (1 warp / row) -------------
__global__ void tangent_kernel(const float* __restrict__ node,
                               const float* __restrict__ h1,
                               const float* __restrict__ h2,
                               const float* __restrict__ h3,
                               const float* __restrict__ curv) {
    int rid  = (blockIdx.x << 3) + (threadIdx.x >> 5);
    int lane = threadIdx.x & 31;
    if (rid >= 4 * NN) return;

    const float* srcp;
    float* dstp;
    if (rid < NN) {
        srcp = node + (size_t)rid * DD;
        dstp = g_tan_node + (size_t)rid * DD;
    } else {
        int t = rid - NN;
        int k = t / NN;
        int n = t - k * NN;
        const float* h = (k == 0) ? h1 : (k == 1) ? h2 : h3;
        srcp = h + (size_t)n * DD;
        dstp = g_th + (size_t)n * (3 * DD) + k * DD;
    }

    float4 x = ((const float4*)srcp)[lane];
    float ss = x.x * x.x + x.y * x.y + x.z * x.z + x.w * x.w;
#pragma unroll
    for (int off = 16; off; off >>= 1) ss += __shfl_xor_sync(0xffffffffu, ss, off);

    float c  = fabsf(curv[0]);
    float sc = sqrtf(c);
    float xn  = fmaxf(sqrtf(ss), 1e-15f);
    float arg = fminf(sc * xn, 1.0f - 1e-5f);
    float alpha = atanhf(arg) / (sc * xn);

    ((float4*)dstp)[lane] =
        make_float4(x.x * alpha, x.y * alpha, x.z * alpha, x.w * alpha);
}

// ---------------- CSR build -------------------------------------------------
__global__ void deg_kernel(const int* __restrict__ dst) {
    int e = blockIdx.x * blockDim.x + threadIdx.x;
    if (e < EE) atomicAdd(&g_deg[dst[e]], 1);
}

__global__ void scan_kernel() {
    __shared__ int wsum[32];
    __shared__ int s_carry;
    int tid = threadIdx.x, lane = tid & 31, w = tid >> 5;
    if (tid == 0) { s_carry = 0; g_rowstart[0] = 0; }
    __syncthreads();
    for (int base = 0; base < NN; base += 1024) {
        int idx = base + tid;
        int v = (idx < NN) ? g_deg[idx] : 0;
        int x = v;
#pragma unroll
        for (int off = 1; off < 32; off <<= 1) {
            int y = __shfl_up_sync(0xffffffffu, x, off);
            if (lane >= off) x += y;
        }
        if (lane == 31) wsum[w] = x;
        __syncthreads();
        if (w == 0) {
            int z = wsum[lane];
#pragma unroll
            for (int off = 1; off < 32; off <<= 1) {
                int y = __shfl_up_sync(0xffffffffu, z, off);
                if (lane >= off) z += y;
            }
            wsum[lane] = z;
        }
        __syncthreads();
        int carry = s_carry;
        int incl  = x + ((w > 0) ? wsum[w - 1] : 0);
        if (idx < NN) {
            g_rowstart[idx + 1] = carry + incl;
            g_cursor[idx]       = carry + incl - v;
        }
        __syncthreads();
        if (tid == 1023) s_carry = carry + incl;
        __syncthreads();
    }
}

__global__ void place_kernel(const int* __restrict__ src,
                             const int* __restrict__ dst) {
    int e = blockIdx.x * blockDim.x + threadIdx.x;
    if (e < EE) {
        int d = dst[e];
        int p = atomicAdd(&g_cursor[d], 1);
        g_csr[p] = src[e];
    }
}

// ---------------- SIMT GEMM: out[n,o] = sum_j in[n,j]*W[o,j] + b[o] ---------
// Weights fully in smem, packed [j/4][o][4] -> conflict-free LDS.128.
// 256 threads: two halves of 128 output-lanes, 8 rows each (16 rows/batch).
template <int K>
__global__ __launch_bounds__(256) void gemm_kernel(const float* __restrict__ bias) {
    extern __shared__ float smem[];
    float* w_s = smem;              // K*128 floats
    float* t_s = smem + K * DD;     // 16*K floats

    const float* in  = (K == DD) ? g_tan_node : g_th;
    const float* Wt  = (K == DD) ? g_Wt1 : g_Wt2;
    float*       out = (K == DD) ? g_transformed : g_conv;

    const int KV = K / 4;
    int tid = threadIdx.x;

    // load packed weights once
    {
        const float4* Wt4 = (const float4*)Wt;
        float4* w4 = (float4*)w_s;
        for (int idx = tid; idx < K * DD / 4; idx += 256) w4[idx] = Wt4[idx];
    }

    int o = tid & 127;
    int half = tid >> 7;
    float b = bias[o];
    const float4* in4 = (const float4*)in;
    const float4* w4  = (const float4*)w_s;
    float4*       t4  = (float4*)t_s;

    for (int base = blockIdx.x * 16; base < NN; base += gridDim.x * 16) {
        __syncthreads();  // weights ready (iter 0) / previous compute done
        for (int idx = tid; idx < 16 * KV; idx += 256) {
            int r = idx / KV;
            int j = idx - r * KV;
            t4[idx] = in4[(size_t)(base + r) * KV + j];
        }
        __syncthreads();

        float acc[8];
#pragma unroll
        for (int r = 0; r < 8; r++) acc[r] = 0.f;

        const float4* trow = t4 + (half * 8) * KV;
#pragma unroll 4
        for (int jo = 0; jo < KV; ++jo) {
            float4 w = w4[jo * DD + o];
#pragma unroll
            for (int r = 0; r < 8; r++) {
                float4 t = trow[r * KV + jo];
                acc[r] = fmaf(t.x, w.x, acc[r]);
                acc[r] = fmaf(t.y, w.y, acc[r]);
                acc[r] = fmaf(t.z, w.z, acc[r]);
                acc[r] = fmaf(t.w, w.w, acc[r]);
            }
        }
#pragma unroll
        for (int r = 0; r < 8; r++) {
            int n = base + half * 8 + r;
            out[(size_t)n * DD + o] = acc[r] + b;
        }
    }
}

// ---------------- gather-sum + neigh/deg + conv add + expmap0 ---------------
// 1 warp per node. tangent_cur = logmap0(expmap0(neigh)) = neigh (exact id).
__global__ void finalize_kernel(const float* __restrict__ curv,
                                float* __restrict__ out) {
    int n = (blockIdx.x * blockDim.x + threadIdx.x) >> 5;
    int lane = threadIdx.x & 31;
    if (n >= NN) return;

    int s = g_rowstart[n];
    int e = g_rowstart[n + 1];
    const float4* T = (const float4*)g_transformed;

    float4 a = make_float4(0.f, 0.f, 0.f, 0.f);
    int p = s;
    for (; p + 4 <= e; p += 4) {
        int i0 = g_csr[p + 0], i1 = g_csr[p + 1];
        int i2 = g_csr[p + 2], i3 = g_csr[p + 3];
        float4 v0 = T[i0 * 32 + lane];
        float4 v1 = T[i1 * 32 + lane];
        float4 v2 = T[i2 * 32 + lane];
        float4 v3 = T[i3 * 32 + lane];
        a.x += (v0.x + v1.x) + (v2.x + v3.x);
        a.y += (v0.y + v1.y) + (v2.y + v3.y);
        a.z += (v0.z + v1.z) + (v2.z + v3.z);
        a.w += (v0.w + v1.w) + (v2.w + v3.w);
    }
    for (; p < e; ++p) {
        int i0 = g_csr[p];
        float4 v0 = T[i0 * 32 + lane];
        a.x += v0.x; a.y += v0.y; a.z += v0.z; a.w += v0.w;
    }

    float inv = (e > s) ? 1.0f / (float)(e - s) : 0.0f;
    float4 cv = ((const float4*)g_conv)[n * 32 + lane];
    float4 v = make_float4(cv.x + a.x * inv, cv.y + a.y * inv,
                           cv.z + a.z * inv, cv.w + a.w * inv);

    float ss = v.x * v.x + v.y * v.y + v.z * v.z + v.w * v.w;
#pragma unroll
    for (int off = 16; off; off >>= 1) ss += __shfl_xor_sync(0xffffffffu, ss, off);

    float c  = fabsf(curv[0]);
    float sc = sqrtf(c);
    float un = fmaxf(sqrtf(ss), 1e-15f);
    float arg = sc * un;
    float f = tanhf(arg) / arg;

    ((float4*)out)[n * 32 + lane] =
        make_float4(v.x * f, v.y * f, v.z * f, v.w * f);
}

// ---------------- launch ----------------------------------------------------
extern "C" void kernel_launch(void* const* d_in, const int* in_sizes, int n_in,
                              void* d_out, int out_size) {
    const float* node   = (const float*)d_in[0];
    const float* h1     = (const float*)d_in[1];
    const float* h2     = (const float*)d_in[2];
    const float* h3     = (const float*)d_in[3];
    const float* lin_w  = (const float*)d_in[4];
    const float* lin_b  = (const float*)d_in[5];
    const float* conv_w = (const float*)d_in[6];
    const float* conv_b = (const float*)d_in[7];
    const float* curv   = (const float*)d_in[8];
    const int*   esrc   = (const int*)d_in[9];
    const int*   edst   = (const int*)d_in[10];
    float* out = (float*)d_out;

    cudaFuncSetAttribute(gemm_kernel<128>,
                         cudaFuncAttributeMaxDynamicSharedMemorySize, 73728);
    cudaFuncSetAttribute(gemm_kernel<384>,
                         cudaFuncAttributeMaxDynamicSharedMemorySize, 221184);

    zero_deg_kernel<<<(NN + 255) / 256, 256>>>();
    tangent_kernel<<<(4 * NN) / 8, 256>>>(node, h1, h2, h3, curv);
    prep_weights_kernel<<<256, 256>>>(lin_w, conv_w);
    deg_kernel<<<(EE + 255) / 256, 256>>>(edst);
    scan_kernel<<<1, 1024>>>();
    place_kernel<<<(EE + 255) / 256, 256>>>(esrc, edst);
    gemm_kernel<128><<<296, 256, 73728>>>(lin_b);
    gemm_kernel<384><<<148, 256, 221184>>>(conv_b);
    finalize_kernel<<<(NN + 7) / 8, 256>>>(curv, out);
}

// round 3
// speedup vs baseline: 1.5016x; 1.5016x over previous
#include <cuda_runtime.h>
#include <cuda_bf16.h>
#include <cstdint>
#include <math.h>

#define NN 50000
#define DD 128
#define EE 625000

// ---------------- scratch (static device allocations) ----------------------
__device__ __nv_bfloat16 g_A1hi[NN * DD];        // logmap0(node) hi
__device__ __nv_bfloat16 g_A1lo[NN * DD];        // logmap0(node) lo
__device__ __nv_bfloat16 g_A2hi[NN * 3 * DD];    // th packed [n][i*3+k] hi
__device__ __nv_bfloat16 g_A2lo[NN * 3 * DD];    // th packed lo
__device__ __nv_bfloat16 g_W1hi[DD * DD];        // lin_w [o][k]
__device__ __nv_bfloat16 g_W1lo[DD * DD];
__device__ __nv_bfloat16 g_W2hi[DD * 3 * DD];    // conv_w [o][i*3+k]
__device__ __nv_bfloat16 g_W2lo[DD * 3 * DD];
__device__ float g_transformed[NN * DD];         // GEMM1 output
__device__ float g_conv[NN * DD];                // GEMM2 output
__device__ int   g_deg[NN];
__device__ int   g_rowstart[NN + 1];
__device__ int   g_cursor[NN];
__device__ int   g_csr[EE];

#define SMEM_SWIZZLE_128B(b) ((b) ^ (((b) >> 3) & 0x70))

__device__ __forceinline__ uint32_t smem_to_u32(const void* p) {
    uint32_t a;
    asm("{ .reg .u64 t; cvta.to.shared.u64 t, %1; cvt.u32.u64 %0, t; }"
        : "=r"(a) : "l"(p));
    return a;
}

__device__ __forceinline__ void cp_async16(uint32_t saddr, const void* gptr) {
    asm volatile("cp.async.cg.shared.global [%0], [%1], 16;"
                 :: "r"(saddr), "l"(gptr) : "memory");
}
__device__ __forceinline__ void cp_commit() {
    asm volatile("cp.async.commit_group;" ::: "memory");
}
template <int N>
__device__ __forceinline__ void cp_wait() {
    asm volatile("cp.async.wait_group %0;" :: "n"(N) : "memory");
}

__device__ __forceinline__ void ldsm_x4(uint32_t* r, uint32_t addr) {
    asm volatile("ldmatrix.sync.aligned.m8n8.x4.shared.b16 {%0,%1,%2,%3}, [%4];"
                 : "=r"(r[0]), "=r"(r[1]), "=r"(r[2]), "=r"(r[3])
                 : "r"(addr));
}

__device__ __forceinline__ void mma_bf16(float* d, const uint32_t* a,
                                         const uint32_t* b) {
    asm volatile(
        "mma.sync.aligned.m16n8k16.row.col.f32.bf16.bf16.f32 "
        "{%0,%1,%2,%3}, {%4,%5,%6,%7}, {%8,%9}, {%0,%1,%2,%3};"
        : "+f"(d[0]), "+f"(d[1]), "+f"(d[2]), "+f"(d[3])
        : "r"(a[0]), "r"(a[1]), "r"(a[2]), "r"(a[3]), "r"(b[0]), "r"(b[1]));
}

// ---------------- small utility kernels ------------------------------------
__global__ void zero_deg_kernel() {
    int i = blockIdx.x * blockDim.x + threadIdx.x;
    if (i < NN) g_deg[i] = 0;
}

__device__ __forceinline__ void split_bf16(float v, __nv_bfloat16& hi, __nv_bfloat16& lo) {
    hi = __float2bfloat16(v);
    lo = __float2bfloat16(v - __bfloat162float(hi));
}

__global__ void prep_weights_kernel(const float* __restrict__ lin_w,
                                    const float* __restrict__ conv_w) {
    int idx = blockIdx.x * blockDim.x + threadIdx.x;
    if (idx < DD * DD) {
        split_bf16(lin_w[idx], g_W1hi[idx], g_W1lo[idx]);
    } else {
        int j = idx - DD * DD;
        split_bf16(conv_w[j], g_W2hi[j], g_W2lo[j]);
    }
}

// ---------------- logmap0 -> bf16 hi/lo (1 warp / row) ----------------------
__global__ void tangent_kernel(const float* __restrict__ node,
                               const float* __restrict__ h1,
                               const float* __restrict__ h2,
                               const float* __restrict__ h3,
                               const float* __restrict__ curv) {
    int rid  = (blockIdx.x << 3) + (threadIdx.x >> 5);
    int lane = threadIdx.x & 31;
    if (rid >= 4 * NN) return;

    const float* srcp;
    int n = 0, k = 0;
    bool is_node = (rid < NN);
    if (is_node) {
        n = rid;
        srcp = node + (size_t)n * DD;
    } else {
        int t = rid - NN;
        k = t / NN;
        n = t - k * NN;
        const float* h = (k == 0) ? h1 : (k == 1) ? h2 : h3;
        srcp = h + (size_t)n * DD;
    }

    float4 x = ((const float4*)srcp)[lane];
    float ss = x.x * x.x + x.y * x.y + x.z * x.z + x.w * x.w;
#pragma unroll
    for (int off = 16; off; off >>= 1) ss += __shfl_xor_sync(0xffffffffu, ss, off);

    float c  = fabsf(curv[0]);
    float sc = sqrtf(c);
    float xn  = fmaxf(sqrtf(ss), 1e-15f);
    float arg = fminf(sc * xn, 1.0f - 1e-5f);
    float alpha = atanhf(arg) / (sc * xn);

    float v[4] = {x.x * alpha, x.y * alpha, x.z * alpha, x.w * alpha};
    __nv_bfloat16 hi[4], lo[4];
#pragma unroll
    for (int t = 0; t < 4; t++) split_bf16(v[t], hi[t], lo[t]);

    if (is_node) {
        union { __nv_bfloat16 b[4]; uint2 u; } ph, pl;
#pragma unroll
        for (int t = 0; t < 4; t++) { ph.b[t] = hi[t]; pl.b[t] = lo[t]; }
        ((uint2*)(g_A1hi + (size_t)n * DD))[lane] = ph.u;
        ((uint2*)(g_A1lo + (size_t)n * DD))[lane] = pl.u;
    } else {
        size_t base = (size_t)n * (3 * DD) + k;
#pragma unroll
        for (int t = 0; t < 4; t++) {
            int i = lane * 4 + t;
            g_A2hi[base + (size_t)i * 3] = hi[t];
            g_A2lo[base + (size_t)i * 3] = lo[t];
        }
    }
}

// ---------------- CSR build -------------------------------------------------
__global__ void deg_kernel(const int* __restrict__ dst) {
    int e = blockIdx.x * blockDim.x + threadIdx.x;
    if (e < EE) atomicAdd(&g_deg[dst[e]], 1);
}

__global__ void scan_kernel() {
    __shared__ int wsum[32];
    __shared__ int s_carry;
    int tid = threadIdx.x, lane = tid & 31, w = tid >> 5;
    if (tid == 0) { s_carry = 0; g_rowstart[0] = 0; }
    __syncthreads();
    for (int base = 0; base < NN; base += 1024) {
        int idx = base + tid;
        int v = (idx < NN) ? g_deg[idx] : 0;
        int x = v;
#pragma unroll
        for (int off = 1; off < 32; off <<= 1) {
            int y = __shfl_up_sync(0xffffffffu, x, off);
            if (lane >= off) x += y;
        }
        if (lane == 31) wsum[w] = x;
        __syncthreads();
        if (w == 0) {
            int z = wsum[lane];
#pragma unroll
            for (int off = 1; off < 32; off <<= 1) {
                int y = __shfl_up_sync(0xffffffffu, z, off);
                if (lane >= off) z += y;
            }
            wsum[lane] = z;
        }
        __syncthreads();
        int carry = s_carry;
        int incl  = x + ((w > 0) ? wsum[w - 1] : 0);
        if (idx < NN) {
            g_rowstart[idx + 1] = carry + incl;
            g_cursor[idx]       = carry + incl - v;
        }
        __syncthreads();
        if (tid == 1023) s_carry = carry + incl;
        __syncthreads();
    }
}

__global__ void place_kernel(const int* __restrict__ src,
                             const int* __restrict__ dst) {
    int e = blockIdx.x * blockDim.x + threadIdx.x;
    if (e < EE) {
        int d = dst[e];
        int p = atomicAdd(&g_cursor[d], 1);
        g_csr[p] = src[e];
    }
}

// ---------------- HMMA GEMM: out[n,o] = sum_j A[n,j]*W[o,j] + b[o] ----------
// fp32 via bf16 hi/lo split, mma.sync m16n8k16 (base ISA, works on compute_103).
// Block: 128x128 C tile, 8 warps (4m x 2n) of 32x64. K staged in 64-chunks,
// double-buffered via cp.async, SW128 swizzle for conflict-free ldmatrix.
static constexpr int ST_AHI = 0;
static constexpr int ST_ALO = 16384;
static constexpr int ST_WHI = 32768;
static constexpr int ST_WLO = 49152;
static constexpr int ST_STRIDE = 65536;
static constexpr int SM_BIAS_OFF = 2 * ST_STRIDE;          // 131072
static constexpr int SM_GEMM_TOTAL = SM_BIAS_OFF + 512;    // 131584

template <int K>
__global__ __launch_bounds__(256)
void gemm_hmma_kernel(const float* __restrict__ bias) {
    constexpr int CH = K / 64;
    constexpr int KV = K / 8;          // uint4 per row
    extern __shared__ char smem[];
    uint32_t sb = smem_to_u32(smem);

    int tid = threadIdx.x;
    int wid = tid >> 5;
    int lane = tid & 31;
    int warp_m = wid & 3;
    int warp_n = wid >> 2;

    const uint4* A4hi = (const uint4*)((K == DD) ? g_A1hi : g_A2hi);
    const uint4* A4lo = (const uint4*)((K == DD) ? g_A1lo : g_A2lo);
    const uint4* W4hi = (const uint4*)((K == DD) ? g_W1hi : g_W2hi);
    const uint4* W4lo = (const uint4*)((K == DD) ? g_W1lo : g_W2lo);
    float* out = (K == DD) ? g_transformed : g_conv;

    if (tid < 128) ((float*)(smem + SM_BIAS_OFF))[tid] = bias[tid];

    int base = blockIdx.x * 128;

    // ---- prefetch helper (16 cp.async of 16B per thread per stage) ----
    auto prefetch = [&](int c, int buf) {
        uint32_t st = sb + buf * ST_STRIDE;
#pragma unroll
        for (int it = 0; it < 4; ++it) {
            int idx = tid + it * 256;       // 0..1023
            int row = idx >> 3;
            int kq  = idx & 7;
            uint32_t off = SMEM_SWIZZLE_128B((uint32_t)(row * 128 + kq * 16));
            int gn = base + row;
            if (gn >= NN) gn = NN - 1;
            size_t gidx = (size_t)gn * KV + c * 8 + kq;
            size_t widx = (size_t)row * KV + c * 8 + kq;
            cp_async16(st + ST_AHI + off, A4hi + gidx);
            cp_async16(st + ST_ALO + off, A4lo + gidx);
            cp_async16(st + ST_WHI + off, W4hi + widx);
            cp_async16(st + ST_WLO + off, W4lo + widx);
        }
        cp_commit();
    };

    float acc[2][8][4];
#pragma unroll
    for (int mi = 0; mi < 2; mi++)
#pragma unroll
        for (int nb = 0; nb < 8; nb++)
#pragma unroll
            for (int q = 0; q < 4; q++) acc[mi][nb][q] = 0.f;

    int g  = lane >> 3;
    int ri = lane & 7;

    prefetch(0, 0);

    for (int c = 0; c < CH; ++c) {
        if (c + 1 < CH) {
            prefetch(c + 1, (c + 1) & 1);
            cp_wait<1>();
        } else {
            cp_wait<0>();
        }
        __syncthreads();

        uint32_t st = sb + (c & 1) * ST_STRIDE;

#pragma unroll
        for (int ks = 0; ks < 4; ++ks) {
            // A fragments (hi and lo), 2 m16 tiles each
            uint32_t a_hi[2][4], a_lo[2][4];
#pragma unroll
            for (int mi = 0; mi < 2; ++mi) {
                int row = warp_m * 32 + mi * 16 + ((g & 1) << 3) + ri;
                int kb  = ks * 32 + ((g >> 1) << 4);
                uint32_t off = SMEM_SWIZZLE_128B((uint32_t)(row * 128 + kb));
                ldsm_x4(a_hi[mi], st + ST_AHI + off);
                ldsm_x4(a_lo[mi], st + ST_ALO + off);
            }
            // 3 passes: (Ahi,Whi), (Ahi,Wlo), (Alo,Whi)
#pragma unroll
            for (int p = 0; p < 3; ++p) {
                uint32_t woff = (p == 1) ? ST_WLO : ST_WHI;
                uint32_t (*af)[4] = (p == 2) ? a_lo : a_hi;
                uint32_t b[8][2];
#pragma unroll
                for (int nb2 = 0; nb2 < 4; ++nb2) {
                    int row = warp_n * 64 + nb2 * 16 + ((g >> 1) << 3) + ri;
                    int kb  = ks * 32 + ((g & 1) << 4);
                    uint32_t off = SMEM_SWIZZLE_128B((uint32_t)(row * 128 + kb));
                    uint32_t r[4];
                    ldsm_x4(r, st + woff + off);
                    b[nb2 * 2 + 0][0] = r[0];
                    b[nb2 * 2 + 0][1] = r[1];
                    b[nb2 * 2 + 1][0] = r[2];
                    b[nb2 * 2 + 1][1] = r[3];
                }
#pragma unroll
                for (int mi = 0; mi < 2; ++mi)
#pragma unroll
                    for (int nb = 0; nb < 8; ++nb)
                        mma_bf16(acc[mi][nb], af[mi], b[nb]);
            }
        }
        __syncthreads();   // protect buffer reuse by next prefetch round
    }

    // ---- epilogue ----
    const float* bias_s = (const float*)(smem + SM_BIAS_OFF);
    int qrow = lane >> 2;
    int qcol = (lane & 3) * 2;
#pragma unroll
    for (int mi = 0; mi < 2; ++mi) {
#pragma unroll
        for (int nb = 0; nb < 8; ++nb) {
            int col = warp_n * 64 + nb * 8 + qcol;
            float b0 = bias_s[col], b1 = bias_s[col + 1];
            int r0 = base + warp_m * 32 + mi * 16 + qrow;
            if (r0 < NN) {
                float2 v0 = make_float2(acc[mi][nb][0] + b0, acc[mi][nb][1] + b1);
                *(float2*)(out + (size_t)r0 * DD + col) = v0;
            }
            int r1 = r0 + 8;
            if (r1 < NN) {
                float2 v1 = make_float2(acc[mi][nb][2] + b0, acc[mi][nb][3] + b1);
                *(float2*)(out + (size_t)r1 * DD + col) = v1;
            }
        }
    }
}

// ---------------- gather-sum + neigh/deg + conv add + expmap0 ---------------
__global__ void finalize_kernel(const float* __restrict__ curv,
                                float* __restrict__ out) {
    int n = (blockIdx.x * blockDim.x + threadIdx.x) >> 5;
    int lane = threadIdx.x & 31;
    if (n >= NN) return;

    int s = g_rowstart[n];
    int e = g_rowstart[n + 1];
    const float4* T = (const float4*)g_transformed;

    float4 a = make_float4(0.f, 0.f, 0.f, 0.f);
    int p = s;
    for (; p + 4 <= e; p += 4) {
        int i0 = g_csr[p + 0], i1 = g_csr[p + 1];
        int i2 = g_csr[p + 2], i3 = g_csr[p + 3];
        float4 v0 = T[i0 * 32 + lane];
        float4 v1 = T[i1 * 32 + lane];
        float4 v2 = T[i2 * 32 + lane];
        float4 v3 = T[i3 * 32 + lane];
        a.x += (v0.x + v1.x) + (v2.x + v3.x);
        a.y += (v0.y + v1.y) + (v2.y + v3.y);
        a.z += (v0.z + v1.z) + (v2.z + v3.z);
        a.w += (v0.w + v1.w) + (v2.w + v3.w);
    }
    for (; p < e; ++p) {
        int i0 = g_csr[p];
        float4 v0 = T[i0 * 32 + lane];
        a.x += v0.x; a.y += v0.y; a.z += v0.z; a.w += v0.w;
    }

    float inv = (e > s) ? 1.0f / (float)(e - s) : 0.0f;
    float4 cv = ((const float4*)g_conv)[n * 32 + lane];
    float4 v = make_float4(cv.x + a.x * inv, cv.y + a.y * inv,
                           cv.z + a.z * inv, cv.w + a.w * inv);

    float ss = v.x * v.x + v.y * v.y + v.z * v.z + v.w * v.w;
#pragma unroll
    for (int off = 16; off; off >>= 1) ss += __shfl_xor_sync(0xffffffffu, ss, off);

    float c  = fabsf(curv[0]);
    float sc = sqrtf(c);
    float un = fmaxf(sqrtf(ss), 1e-15f);
    float arg = sc * un;
    float f = tanhf(arg) / arg;

    ((float4*)out)[n * 32 + lane] =
        make_float4(v.x * f, v.y * f, v.z * f, v.w * f);
}

// ---------------- launch ----------------------------------------------------
extern "C" void kernel_launch(void* const* d_in, const int* in_sizes, int n_in,
                              void* d_out, int out_size) {
    const float* node   = (const float*)d_in[0];
    const float* h1     = (const float*)d_in[1];
    const float* h2     = (const float*)d_in[2];
    const float* h3     = (const float*)d_in[3];
    const float* lin_w  = (const float*)d_in[4];
    const float* lin_b  = (const float*)d_in[5];
    const float* conv_w = (const float*)d_in[6];
    const float* conv_b = (const float*)d_in[7];
    const float* curv   = (const float*)d_in[8];
    const int*   esrc   = (const int*)d_in[9];
    const int*   edst   = (const int*)d_in[10];
    float* out = (float*)d_out;

    cudaFuncSetAttribute(gemm_hmma_kernel<128>,
                         cudaFuncAttributeMaxDynamicSharedMemorySize, SM_GEMM_TOTAL);
    cudaFuncSetAttribute(gemm_hmma_kernel<384>,
                         cudaFuncAttributeMaxDynamicSharedMemorySize, SM_GEMM_TOTAL);

    int gemm_grid = (NN + 127) / 128;   // 391

    zero_deg_kernel<<<(NN + 255) / 256, 256>>>();
    tangent_kernel<<<(4 * NN) / 8, 256>>>(node, h1, h2, h3, curv);
    prep_weights_kernel<<<(DD * DD + 3 * DD * DD) / 256, 256>>>(lin_w, conv_w);
    deg_kernel<<<(EE + 255) / 256, 256>>>(edst);
    scan_kernel<<<1, 1024>>>();
    place_kernel<<<(EE + 255) / 256, 256>>>(esrc, edst);
    gemm_hmma_kernel<128><<<gemm_grid, 256, SM_GEMM_TOTAL>>>(lin_b);
    gemm_hmma_kernel<384><<<gemm_grid, 256, SM_GEMM_TOTAL>>>(conv_b);
    finalize_kernel<<<(NN + 7) / 8, 256>>>(curv, out);
}

// round 4
// speedup vs baseline: 2.7970x; 1.8627x over previous
#include <cuda_runtime.h>
#include <cuda_bf16.h>
#include <cstdint>
#include <math.h>

#define NN 50000
#define DD 128
#define EE 625000
#define SCAN_BLOCKS 49   // ceil(50000/1024)

// ---------------- scratch (static device allocations) ----------------------
__device__ __nv_bfloat16 g_A1hi[NN * DD];        // logmap0(node) hi
__device__ __nv_bfloat16 g_A1lo[NN * DD];        // logmap0(node) lo
__device__ __nv_bfloat16 g_A2hi[NN * 3 * DD];    // th packed [n][k*128+i] hi
__device__ __nv_bfloat16 g_A2lo[NN * 3 * DD];    // th packed lo
__device__ __nv_bfloat16 g_W1hi[DD * DD];        // lin_w [o][k]
__device__ __nv_bfloat16 g_W1lo[DD * DD];
__device__ __nv_bfloat16 g_W2hi[DD * 3 * DD];    // conv_w packed [o][k*128+i]
__device__ __nv_bfloat16 g_W2lo[DD * 3 * DD];
__device__ float g_transformed[NN * DD];         // GEMM1 output
__device__ float g_conv[NN * DD];                // GEMM2 output
__device__ int   g_deg[NN];
__device__ int   g_rowstart[NN + 1];
__device__ int   g_cursor[NN];
__device__ int   g_csr[EE];
__device__ int   g_bsum[SCAN_BLOCKS];
__device__ int   g_boff[SCAN_BLOCKS];

#define SMEM_SWIZZLE_128B(b) ((b) ^ (((b) >> 3) & 0x70))

__device__ __forceinline__ uint32_t smem_to_u32(const void* p) {
    uint32_t a;
    asm("{ .reg .u64 t; cvta.to.shared.u64 t, %1; cvt.u32.u64 %0, t; }"
        : "=r"(a) : "l"(p));
    return a;
}

__device__ __forceinline__ void cp_async16(uint32_t saddr, const void* gptr) {
    asm volatile("cp.async.cg.shared.global [%0], [%1], 16;"
                 :: "r"(saddr), "l"(gptr) : "memory");
}
__device__ __forceinline__ void cp_commit() {
    asm volatile("cp.async.commit_group;" ::: "memory");
}
template <int N>
__device__ __forceinline__ void cp_wait() {
    asm volatile("cp.async.wait_group %0;" :: "n"(N) : "memory");
}

__device__ __forceinline__ void ldsm_x4(uint32_t* r, uint32_t addr) {
    asm volatile("ldmatrix.sync.aligned.m8n8.x4.shared.b16 {%0,%1,%2,%3}, [%4];"
                 : "=r"(r[0]), "=r"(r[1]), "=r"(r[2]), "=r"(r[3])
                 : "r"(addr));
}

__device__ __forceinline__ void mma_bf16(float* d, const uint32_t* a,
                                         const uint32_t* b) {
    asm volatile(
        "mma.sync.aligned.m16n8k16.row.col.f32.bf16.bf16.f32 "
        "{%0,%1,%2,%3}, {%4,%5,%6,%7}, {%8,%9}, {%0,%1,%2,%3};"
        : "+f"(d[0]), "+f"(d[1]), "+f"(d[2]), "+f"(d[3])
        : "r"(a[0]), "r"(a[1]), "r"(a[2]), "r"(a[3]), "r"(b[0]), "r"(b[1]));
}

__device__ __forceinline__ void split_bf16(float v, __nv_bfloat16& hi, __nv_bfloat16& lo) {
    hi = __float2bfloat16(v);
    lo = __float2bfloat16(v - __bfloat162float(hi));
}

// ---------------- prep: zero deg + pack/split weights -----------------------
__global__ void prep_kernel(const float* __restrict__ lin_w,
                            const float* __restrict__ conv_w) {
    int idx = blockIdx.x * blockDim.x + threadIdx.x;   // 0 .. 65535
    if (idx < NN) g_deg[idx] = 0;
    if (idx < DD * DD) {
        split_bf16(lin_w[idx], g_W1hi[idx], g_W1lo[idx]);
    } else if (idx < DD * DD + 3 * DD * DD) {
        int t = idx - DD * DD;          // target index in [o][k*128+i]
        int o = t / (3 * DD);
        int r = t - o * (3 * DD);
        int k = r >> 7, i = r & 127;
        split_bf16(conv_w[(o * DD + i) * 3 + k], g_W2hi[t], g_W2lo[t]);
    }
}

// ---------------- logmap0 -> bf16 hi/lo (1 warp / row) ----------------------
__global__ void tangent_kernel(const float* __restrict__ node,
                               const float* __restrict__ h1,
                               const float* __restrict__ h2,
                               const float* __restrict__ h3,
                               const float* __restrict__ curv) {
    int rid  = (blockIdx.x << 3) + (threadIdx.x >> 5);
    int lane = threadIdx.x & 31;
    if (rid >= 4 * NN) return;

    const float* srcp;
    int n = 0, k = 0;
    bool is_node = (rid < NN);
    if (is_node) {
        n = rid;
        srcp = node + (size_t)n * DD;
    } else {
        int t = rid - NN;
        k = t / NN;
        n = t - k * NN;
        const float* h = (k == 0) ? h1 : (k == 1) ? h2 : h3;
        srcp = h + (size_t)n * DD;
    }

    float4 x = ((const float4*)srcp)[lane];
    float ss = x.x * x.x + x.y * x.y + x.z * x.z + x.w * x.w;
#pragma unroll
    for (int off = 16; off; off >>= 1) ss += __shfl_xor_sync(0xffffffffu, ss, off);

    float c  = fabsf(curv[0]);
    float sc = sqrtf(c);
    float xn  = fmaxf(sqrtf(ss), 1e-15f);
    float arg = fminf(sc * xn, 1.0f - 1e-5f);
    float alpha = atanhf(arg) / (sc * xn);

    float v[4] = {x.x * alpha, x.y * alpha, x.z * alpha, x.w * alpha};
    union { __nv_bfloat16 b[4]; uint2 u; } ph, pl;
#pragma unroll
    for (int t = 0; t < 4; t++) split_bf16(v[t], ph.b[t], pl.b[t]);

    if (is_node) {
        ((uint2*)(g_A1hi + (size_t)n * DD))[lane] = ph.u;
        ((uint2*)(g_A1lo + (size_t)n * DD))[lane] = pl.u;
    } else {
        // plane-contiguous: row n, element j = k*128 + lane*4 (.. +3)
        size_t off = (size_t)n * (3 * DD) + k * DD + lane * 4;
        *(uint2*)(g_A2hi + off) = ph.u;
        *(uint2*)(g_A2lo + off) = pl.u;
    }
}

// ---------------- CSR build -------------------------------------------------
__global__ void deg_kernel(const int* __restrict__ dst) {
    int e = blockIdx.x * blockDim.x + threadIdx.x;
    if (e < EE) atomicAdd(&g_deg[dst[e]], 1);
}

// phase 1: per-block (1024-elt) sums
__global__ __launch_bounds__(1024) void scan1_kernel() {
    __shared__ int wsum[32];
    int tid = threadIdx.x, lane = tid & 31, w = tid >> 5;
    int idx = blockIdx.x * 1024 + tid;
    int v = (idx < NN) ? g_deg[idx] : 0;
    int x = v;
#pragma unroll
    for (int off = 16; off; off >>= 1) x += __shfl_xor_sync(0xffffffffu, x, off);
    if (lane == 0) wsum[w] = x;
    __syncthreads();
    if (w == 0) {
        int z = (lane < 32) ? wsum[lane] : 0;
#pragma unroll
        for (int off = 16; off; off >>= 1) z += __shfl_xor_sync(0xffffffffu, z, off);
        if (lane == 0) g_bsum[blockIdx.x] = z;
    }
}

// phase 2: exclusive scan of SCAN_BLOCKS sums (single warp-ish block)
__global__ void scan2_kernel() {
    int tid = threadIdx.x;   // 64 threads
    int lane = tid & 31, w = tid >> 5;
    __shared__ int warp_tot[2];
    int v = (tid < SCAN_BLOCKS) ? g_bsum[tid] : 0;
    int x = v;
#pragma unroll
    for (int off = 1; off < 32; off <<= 1) {
        int y = __shfl_up_sync(0xffffffffu, x, off);
        if (lane >= off) x += y;
    }
    if (lane == 31) warp_tot[w] = x;
    __syncthreads();
    int incl = x + ((w == 1) ? warp_tot[0] : 0);
    if (tid < SCAN_BLOCKS) g_boff[tid] = incl - v;   // exclusive
    if (tid == 0) g_rowstart[0] = 0;
}

// phase 3: block-local scan + offset -> rowstart / cursor
__global__ __launch_bounds__(1024) void scan3_kernel() {
    __shared__ int wsum[32];
    int tid = threadIdx.x, lane = tid & 31, w = tid >> 5;
    int idx = blockIdx.x * 1024 + tid;
    int v = (idx < NN) ? g_deg[idx] : 0;
    int x = v;
#pragma unroll
    for (int off = 1; off < 32; off <<= 1) {
        int y = __shfl_up_sync(0xffffffffu, x, off);
        if (lane >= off) x += y;
    }
    if (lane == 31) wsum[w] = x;
    __syncthreads();
    if (w == 0) {
        int z = wsum[lane];
#pragma unroll
        for (int off = 1; off < 32; off <<= 1) {
            int y = __shfl_up_sync(0xffffffffu, z, off);
            if (lane >= off) z += y;
        }
        wsum[lane] = z;
    }
    __syncthreads();
    int incl = x + ((w > 0) ? wsum[w - 1] : 0) + g_boff[blockIdx.x];
    if (idx < NN) {
        g_rowstart[idx + 1] = incl;
        g_cursor[idx]       = incl - v;
    }
}

__global__ void place_kernel(const int* __restrict__ src,
                             const int* __restrict__ dst) {
    int e = blockIdx.x * blockDim.x + threadIdx.x;
    if (e < EE) {
        int d = dst[e];
        int p = atomicAdd(&g_cursor[d], 1);
        g_csr[p] = src[e];
    }
}

// ---------------- HMMA GEMM: out[n,o] = sum_j A[n,j]*W[o,j] + b[o] ----------
static constexpr int ST_AHI = 0;
static constexpr int ST_ALO = 16384;
static constexpr int ST_WHI = 32768;
static constexpr int ST_WLO = 49152;
static constexpr int ST_STRIDE = 65536;
static constexpr int SM_BIAS_OFF = 2 * ST_STRIDE;          // 131072
static constexpr int SM_GEMM_TOTAL = SM_BIAS_OFF + 512;    // 131584

template <int K>
__global__ __launch_bounds__(256)
void gemm_hmma_kernel(const float* __restrict__ bias) {
    constexpr int CH = K / 64;
    constexpr int KV = K / 8;          // uint4 per row
    extern __shared__ char smem[];
    uint32_t sb = smem_to_u32(smem);

    int tid = threadIdx.x;
    int wid = tid >> 5;
    int lane = tid & 31;
    int warp_m = wid & 3;
    int warp_n = wid >> 2;

    const uint4* A4hi = (const uint4*)((K == DD) ? g_A1hi : g_A2hi);
    const uint4* A4lo = (const uint4*)((K == DD) ? g_A1lo : g_A2lo);
    const uint4* W4hi = (const uint4*)((K == DD) ? g_W1hi : g_W2hi);
    const uint4* W4lo = (const uint4*)((K == DD) ? g_W1lo : g_W2lo);
    float* out = (K == DD) ? g_transformed : g_conv;

    if (tid < 128) ((float*)(smem + SM_BIAS_OFF))[tid] = bias[tid];

    int base = blockIdx.x * 128;

    auto prefetch = [&](int c, int buf) {
        uint32_t st = sb + buf * ST_STRIDE;
#pragma unroll
        for (int it = 0; it < 4; ++it) {
            int idx = tid + it * 256;       // 0..1023
            int row = idx >> 3;
            int kq  = idx & 7;
            uint32_t off = SMEM_SWIZZLE_128B((uint32_t)(row * 128 + kq * 16));
            int gn = base + row;
            if (gn >= NN) gn = NN - 1;
            size_t gidx = (size_t)gn * KV + c * 8 + kq;
            size_t widx = (size_t)row * KV + c * 8 + kq;
            cp_async16(st + ST_AHI + off, A4hi + gidx);
            cp_async16(st + ST_ALO + off, A4lo + gidx);
            cp_async16(st + ST_WHI + off, W4hi + widx);
            cp_async16(st + ST_WLO + off, W4lo + widx);
        }
        cp_commit();
    };

    float acc[2][8][4];
#pragma unroll
    for (int mi = 0; mi < 2; mi++)
#pragma unroll
        for (int nb = 0; nb < 8; nb++)
#pragma unroll
            for (int q = 0; q < 4; q++) acc[mi][nb][q] = 0.f;

    int g  = lane >> 3;
    int ri = lane & 7;

    prefetch(0, 0);

    for (int c = 0; c < CH; ++c) {
        if (c + 1 < CH) {
            prefetch(c + 1, (c + 1) & 1);
            cp_wait<1>();
        } else {
            cp_wait<0>();
        }
        __syncthreads();

        uint32_t st = sb + (c & 1) * ST_STRIDE;

#pragma unroll
        for (int ks = 0; ks < 4; ++ks) {
            uint32_t a_hi[2][4], a_lo[2][4];
#pragma unroll
            for (int mi = 0; mi < 2; ++mi) {
                int row = warp_m * 32 + mi * 16 + ((g & 1) << 3) + ri;
                int kb  = ks * 32 + ((g >> 1) << 4);
                uint32_t off = SMEM_SWIZZLE_128B((uint32_t)(row * 128 + kb));
                ldsm_x4(a_hi[mi], st + ST_AHI + off);
                ldsm_x4(a_lo[mi], st + ST_ALO + off);
            }
#pragma unroll
            for (int p = 0; p < 3; ++p) {
                uint32_t woff = (p == 1) ? ST_WLO : ST_WHI;
                uint32_t (*af)[4] = (p == 2) ? a_lo : a_hi;
                uint32_t b[8][2];
#pragma unroll
                for (int nb2 = 0; nb2 < 4; ++nb2) {
                    int row = warp_n * 64 + nb2 * 16 + ((g >> 1) << 3) + ri;
                    int kb  = ks * 32 + ((g & 1) << 4);
                    uint32_t off = SMEM_SWIZZLE_128B((uint32_t)(row * 128 + kb));
                    uint32_t r[4];
                    ldsm_x4(r, st + woff + off);
                    b[nb2 * 2 + 0][0] = r[0];
                    b[nb2 * 2 + 0][1] = r[1];
                    b[nb2 * 2 + 1][0] = r[2];
                    b[nb2 * 2 + 1][1] = r[3];
                }
#pragma unroll
                for (int mi = 0; mi < 2; ++mi)
#pragma unroll
                    for (int nb = 0; nb < 8; ++nb)
                        mma_bf16(acc[mi][nb], af[mi], b[nb]);
            }
        }
        __syncthreads();
    }

    const float* bias_s = (const float*)(smem + SM_BIAS_OFF);
    int qrow = lane >> 2;
    int qcol = (lane & 3) * 2;
#pragma unroll
    for (int mi = 0; mi < 2; ++mi) {
#pragma unroll
        for (int nb = 0; nb < 8; ++nb) {
            int col = warp_n * 64 + nb * 8 + qcol;
            float b0 = bias_s[col], b1 = bias_s[col + 1];
            int r0 = base + warp_m * 32 + mi * 16 + qrow;
            if (r0 < NN) {
                float2 v0 = make_float2(acc[mi][nb][0] + b0, acc[mi][nb][1] + b1);
                *(float2*)(out + (size_t)r0 * DD + col) = v0;
            }
            int r1 = r0 + 8;
            if (r1 < NN) {
                float2 v1 = make_float2(acc[mi][nb][2] + b0, acc[mi][nb][3] + b1);
                *(float2*)(out + (size_t)r1 * DD + col) = v1;
            }
        }
    }
}

// ---------------- gather-sum + neigh/deg + conv add + expmap0 ---------------
__global__ void finalize_kernel(const float* __restrict__ curv,
                                float* __restrict__ out) {
    int n = (blockIdx.x * blockDim.x + threadIdx.x) >> 5;
    int lane = threadIdx.x & 31;
    if (n >= NN) return;

    int s = g_rowstart[n];
    int e = g_rowstart[n + 1];
    const float4* T = (const float4*)g_transformed;

    float4 a = make_float4(0.f, 0.f, 0.f, 0.f);
    int p = s;
    for (; p + 4 <= e; p += 4) {
        int i0 = g_csr[p + 0], i1 = g_csr[p + 1];
        int i2 = g_csr[p + 2], i3 = g_csr[p + 3];
        float4 v0 = T[i0 * 32 + lane];
        float4 v1 = T[i1 * 32 + lane];
        float4 v2 = T[i2 * 32 + lane];
        float4 v3 = T[i3 * 32 + lane];
        a.x += (v0.x + v1.x) + (v2.x + v3.x);
        a.y += (v0.y + v1.y) + (v2.y + v3.y);
        a.z += (v0.z + v1.z) + (v2.z + v3.z);
        a.w += (v0.w + v1.w) + (v2.w + v3.w);
    }
    for (; p < e; ++p) {
        int i0 = g_csr[p];
        float4 v0 = T[i0 * 32 + lane];
        a.x += v0.x; a.y += v0.y; a.z += v0.z; a.w += v0.w;
    }

    float inv = (e > s) ? 1.0f / (float)(e - s) : 0.0f;
    float4 cv = ((const float4*)g_conv)[n * 32 + lane];
    float4 v = make_float4(cv.x + a.x * inv, cv.y + a.y * inv,
                           cv.z + a.z * inv, cv.w + a.w * inv);

    float ss = v.x * v.x + v.y * v.y + v.z * v.z + v.w * v.w;
#pragma unroll
    for (int off = 16; off; off >>= 1) ss += __shfl_xor_sync(0xffffffffu, ss, off);

    float c  = fabsf(curv[0]);
    float sc = sqrtf(c);
    float un = fmaxf(sqrtf(ss), 1e-15f);
    float arg = sc * un;
    float f = tanhf(arg) / arg;

    ((float4*)out)[n * 32 + lane] =
        make_float4(v.x * f, v.y * f, v.z * f, v.w * f);
}

// ---------------- launch ----------------------------------------------------
extern "C" void kernel_launch(void* const* d_in, const int* in_sizes, int n_in,
                              void* d_out, int out_size) {
    const float* node   = (const float*)d_in[0];
    const float* h1     = (const float*)d_in[1];
    const float* h2     = (const float*)d_in[2];
    const float* h3     = (const float*)d_in[3];
    const float* lin_w  = (const float*)d_in[4];
    const float* lin_b  = (const float*)d_in[5];
    const float* conv_w = (const float*)d_in[6];
    const float* conv_b = (const float*)d_in[7];
    const float* curv   = (const float*)d_in[8];
    const int*   esrc   = (const int*)d_in[9];
    const int*   edst   = (const int*)d_in[10];
    float* out = (float*)d_out;

    cudaFuncSetAttribute(gemm_hmma_kernel<128>,
                         cudaFuncAttributeMaxDynamicSharedMemorySize, SM_GEMM_TOTAL);
    cudaFuncSetAttribute(gemm_hmma_kernel<384>,
                         cudaFuncAttributeMaxDynamicSharedMemorySize, SM_GEMM_TOTAL);

    int gemm_grid = (NN + 127) / 128;   // 391

    prep_kernel<<<(DD * DD + 3 * DD * DD + 255) / 256, 256>>>(lin_w, conv_w);
    tangent_kernel<<<(4 * NN) / 8, 256>>>(node, h1, h2, h3, curv);
    deg_kernel<<<(EE + 255) / 256, 256>>>(edst);
    scan1_kernel<<<SCAN_BLOCKS, 1024>>>();
    scan2_kernel<<<1, 64>>>();
    scan3_kernel<<<SCAN_BLOCKS, 1024>>>();
    place_kernel<<<(EE + 255) / 256, 256>>>(esrc, edst);
    gemm_hmma_kernel<128><<<gemm_grid, 256, SM_GEMM_TOTAL>>>(lin_b);
    gemm_hmma_kernel<384><<<gemm_grid, 256, SM_GEMM_TOTAL>>>(conv_b);
    finalize_kernel<<<(NN + 7) / 8, 256>>>(curv, out);
}

// round 5
// speedup vs baseline: 2.8691x; 1.0258x over previous
#include <cuda_runtime.h>
#include <cuda_bf16.h>
#include <cstdint>
#include <math.h>

#define NN 50000
#define DD 128
#define EE 625000
#define SCAN_BLOCKS 49   // ceil(50000/1024)
#define DEG_BLOCKS ((EE + 255) / 256)      // 2442
#define TAN_BLOCKS ((4 * NN) / 8)          // 25000
#define G1_BLOCKS ((NN + 127) / 128)       // 391

// ---------------- scratch (static device allocations) ----------------------
__device__ __nv_bfloat16 g_A1hi[NN * DD];
__device__ __nv_bfloat16 g_A1lo[NN * DD];
__device__ __nv_bfloat16 g_A2hi[NN * 3 * DD];    // [n][k*128+i]
__device__ __nv_bfloat16 g_A2lo[NN * 3 * DD];
__device__ __nv_bfloat16 g_W1hi[DD * DD];
__device__ __nv_bfloat16 g_W1lo[DD * DD];
__device__ __nv_bfloat16 g_W2hi[DD * 3 * DD];    // [o][k*128+i]
__device__ __nv_bfloat16 g_W2lo[DD * 3 * DD];
__device__ float g_transformed[NN * DD];
__device__ float g_conv[NN * DD];
__device__ int   g_deg[NN];
__device__ int   g_rowstart[NN + 1];
__device__ int   g_cursor[NN];
__device__ int   g_csr[EE];
__device__ int   g_bsum[SCAN_BLOCKS];
__device__ int   g_boff[SCAN_BLOCKS];
__device__ int   g_ticket;

#define SMEM_SWIZZLE_128B(b) ((b) ^ (((b) >> 3) & 0x70))

__device__ __forceinline__ uint32_t smem_to_u32(const void* p) {
    uint32_t a;
    asm("{ .reg .u64 t; cvta.to.shared.u64 t, %1; cvt.u32.u64 %0, t; }"
        : "=r"(a) : "l"(p));
    return a;
}
__device__ __forceinline__ void cp_async16(uint32_t saddr, const void* gptr) {
    asm volatile("cp.async.cg.shared.global [%0], [%1], 16;"
                 :: "r"(saddr), "l"(gptr) : "memory");
}
__device__ __forceinline__ void cp_commit() {
    asm volatile("cp.async.commit_group;" ::: "memory");
}
template <int N>
__device__ __forceinline__ void cp_wait() {
    asm volatile("cp.async.wait_group %0;" :: "n"(N) : "memory");
}
__device__ __forceinline__ void ldsm_x4(uint32_t* r, uint32_t addr) {
    asm volatile("ldmatrix.sync.aligned.m8n8.x4.shared.b16 {%0,%1,%2,%3}, [%4];"
                 : "=r"(r[0]), "=r"(r[1]), "=r"(r[2]), "=r"(r[3])
                 : "r"(addr));
}
__device__ __forceinline__ void mma_bf16(float* d, const uint32_t* a,
                                         const uint32_t* b) {
    asm volatile(
        "mma.sync.aligned.m16n8k16.row.col.f32.bf16.bf16.f32 "
        "{%0,%1,%2,%3}, {%4,%5,%6,%7}, {%8,%9}, {%0,%1,%2,%3};"
        : "+f"(d[0]), "+f"(d[1]), "+f"(d[2]), "+f"(d[3])
        : "r"(a[0]), "r"(a[1]), "r"(a[2]), "r"(a[3]), "r"(b[0]), "r"(b[1]));
}
__device__ __forceinline__ void split_bf16(float v, __nv_bfloat16& hi, __nv_bfloat16& lo) {
    hi = __float2bfloat16(v);
    lo = __float2bfloat16(v - __bfloat162float(hi));
}

// ---------------- K1: prep (zero deg/ticket + pack/split weights) -----------
__global__ void prep_kernel(const float* __restrict__ lin_w,
                            const float* __restrict__ conv_w) {
    int idx = blockIdx.x * blockDim.x + threadIdx.x;   // 0 .. 65535
    if (idx == 0) g_ticket = 0;
    if (idx < NN) g_deg[idx] = 0;
    if (idx < DD * DD) {
        split_bf16(lin_w[idx], g_W1hi[idx], g_W1lo[idx]);
    } else if (idx < DD * DD + 3 * DD * DD) {
        int t = idx - DD * DD;          // target index in [o][k*128+i]
        int o = t / (3 * DD);
        int r = t - o * (3 * DD);
        int k = r >> 7, i = r & 127;
        split_bf16(conv_w[(o * DD + i) * 3 + k], g_W2hi[t], g_W2lo[t]);
    }
}

// ---------------- K2: fused deg-count + logmap0->bf16 hi/lo -----------------
__global__ void tangent_deg_kernel(const float* __restrict__ node,
                                   const float* __restrict__ h1,
                                   const float* __restrict__ h2,
                                   const float* __restrict__ h3,
                                   const float* __restrict__ curv,
                                   const int* __restrict__ edst) {
    if (blockIdx.x < DEG_BLOCKS) {
        int e = blockIdx.x * 256 + threadIdx.x;
        if (e < EE) atomicAdd(&g_deg[edst[e]], 1);
        return;
    }
    int rid  = ((blockIdx.x - DEG_BLOCKS) << 3) + (threadIdx.x >> 5);
    int lane = threadIdx.x & 31;
    if (rid >= 4 * NN) return;

    const float* srcp;
    int n = 0, k = 0;
    bool is_node = (rid < NN);
    if (is_node) {
        n = rid;
        srcp = node + (size_t)n * DD;
    } else {
        int t = rid - NN;
        k = t / NN;
        n = t - k * NN;
        const float* h = (k == 0) ? h1 : (k == 1) ? h2 : h3;
        srcp = h + (size_t)n * DD;
    }

    float4 x = ((const float4*)srcp)[lane];
    float ss = x.x * x.x + x.y * x.y + x.z * x.z + x.w * x.w;
#pragma unroll
    for (int off = 16; off; off >>= 1) ss += __shfl_xor_sync(0xffffffffu, ss, off);

    float c  = fabsf(curv[0]);
    float sc = sqrtf(c);
    float xn  = fmaxf(sqrtf(ss), 1e-15f);
    float arg = fminf(sc * xn, 1.0f - 1e-5f);
    float alpha = atanhf(arg) / (sc * xn);

    float v[4] = {x.x * alpha, x.y * alpha, x.z * alpha, x.w * alpha};
    union { __nv_bfloat16 b[4]; uint2 u; } ph, pl;
#pragma unroll
    for (int t = 0; t < 4; t++) split_bf16(v[t], ph.b[t], pl.b[t]);

    if (is_node) {
        ((uint2*)(g_A1hi + (size_t)n * DD))[lane] = ph.u;
        ((uint2*)(g_A1lo + (size_t)n * DD))[lane] = pl.u;
    } else {
        size_t off = (size_t)n * (3 * DD) + k * DD + lane * 4;
        *(uint2*)(g_A2hi + off) = ph.u;
        *(uint2*)(g_A2lo + off) = pl.u;
    }
}

// ---------------- K3: scan phase 1 + (last block) phase 2 -------------------
__global__ __launch_bounds__(1024) void scan12_kernel() {
    __shared__ int wsum[32];
    __shared__ int s_last;
    int tid = threadIdx.x, lane = tid & 31, w = tid >> 5;
    int idx = blockIdx.x * 1024 + tid;
    int v = (idx < NN) ? g_deg[idx] : 0;
    int x = v;
#pragma unroll
    for (int off = 16; off; off >>= 1) x += __shfl_xor_sync(0xffffffffu, x, off);
    if (lane == 0) wsum[w] = x;
    __syncthreads();
    if (w == 0) {
        int z = wsum[lane];
#pragma unroll
        for (int off = 16; off; off >>= 1) z += __shfl_xor_sync(0xffffffffu, z, off);
        if (lane == 0) g_bsum[blockIdx.x] = z;
    }
    // last arriving block performs the 49-element exclusive scan
    __threadfence();
    if (tid == 0) {
        int t = atomicAdd(&g_ticket, 1);
        s_last = (t == (int)gridDim.x - 1);
    }
    __syncthreads();
    if (s_last && tid < 64) {
        __shared__ int warp_tot[2];
        int vv = (tid < SCAN_BLOCKS) ? g_bsum[tid] : 0;
        int xx = vv;
#pragma unroll
        for (int off = 1; off < 32; off <<= 1) {
            int y = __shfl_up_sync(0xffffffffu, xx, off);
            if (lane >= off) xx += y;
        }
        if (lane == 31) warp_tot[w] = xx;
        __syncwarp();
        if (w == 1) {
            // warp 1 needs warp 0's total; both warps are in tid<64 branch
        }
        __syncthreads();
        int incl = xx + ((w == 1) ? warp_tot[0] : 0);
        if (tid < SCAN_BLOCKS) g_boff[tid] = incl - vv;
        if (tid == 0) g_rowstart[0] = 0;
    }
}

// ---------------- K4: block-local scan + offset -> rowstart / cursor --------
__global__ __launch_bounds__(1024) void scan3_kernel() {
    __shared__ int wsum[32];
    int tid = threadIdx.x, lane = tid & 31, w = tid >> 5;
    int idx = blockIdx.x * 1024 + tid;
    int v = (idx < NN) ? g_deg[idx] : 0;
    int x = v;
#pragma unroll
    for (int off = 1; off < 32; off <<= 1) {
        int y = __shfl_up_sync(0xffffffffu, x, off);
        if (lane >= off) x += y;
    }
    if (lane == 31) wsum[w] = x;
    __syncthreads();
    if (w == 0) {
        int z = wsum[lane];
#pragma unroll
        for (int off = 1; off < 32; off <<= 1) {
            int y = __shfl_up_sync(0xffffffffu, z, off);
            if (lane >= off) z += y;
        }
        wsum[lane] = z;
    }
    __syncthreads();
    int incl = x + ((w > 0) ? wsum[w - 1] : 0) + g_boff[blockIdx.x];
    if (idx < NN) {
        g_rowstart[idx + 1] = incl;
        g_cursor[idx]       = incl - v;
    }
}

// ---------------- K5: place edges into CSR ----------------------------------
__global__ void place_kernel(const int* __restrict__ src,
                             const int* __restrict__ dst) {
    int e = blockIdx.x * blockDim.x + threadIdx.x;
    if (e < EE) {
        int d = dst[e];
        int p = atomicAdd(&g_cursor[d], 1);
        g_csr[p] = src[e];
    }
}

// ---------------- K6: fused HMMA GEMMs --------------------------------------
static constexpr int ST_AHI = 0;
static constexpr int ST_ALO = 16384;
static constexpr int ST_WHI = 32768;
static constexpr int ST_WLO = 49152;
static constexpr int ST_STRIDE = 65536;
static constexpr int SM_BIAS_OFF = 2 * ST_STRIDE;          // 131072
static constexpr int SM_GEMM_TOTAL = SM_BIAS_OFF + 512;    // 131584

template <int K>
__device__ __forceinline__ void gemm_body(
    int blk, char* smem, uint32_t sb,
    const __nv_bfloat16* Ahi, const __nv_bfloat16* Alo,
    const __nv_bfloat16* Whi, const __nv_bfloat16* Wlo,
    float* out, const float* bias) {
    constexpr int CH = K / 64;
    constexpr int KV = K / 8;

    int tid = threadIdx.x;
    int wid = tid >> 5;
    int lane = tid & 31;
    int warp_m = wid & 3;
    int warp_n = wid >> 2;

    const uint4* A4hi = (const uint4*)Ahi;
    const uint4* A4lo = (const uint4*)Alo;
    const uint4* W4hi = (const uint4*)Whi;
    const uint4* W4lo = (const uint4*)Wlo;

    if (tid < 128) ((float*)(smem + SM_BIAS_OFF))[tid] = bias[tid];

    int base = blk * 128;

    auto prefetch = [&](int c, int buf) {
        uint32_t st = sb + buf * ST_STRIDE;
#pragma unroll
        for (int it = 0; it < 4; ++it) {
            int idx = tid + it * 256;
            int row = idx >> 3;
            int kq  = idx & 7;
            uint32_t off = SMEM_SWIZZLE_128B((uint32_t)(row * 128 + kq * 16));
            int gn = base + row;
            if (gn >= NN) gn = NN - 1;
            size_t gidx = (size_t)gn * KV + c * 8 + kq;
            size_t widx = (size_t)row * KV + c * 8 + kq;
            cp_async16(st + ST_AHI + off, A4hi + gidx);
            cp_async16(st + ST_ALO + off, A4lo + gidx);
            cp_async16(st + ST_WHI + off, W4hi + widx);
            cp_async16(st + ST_WLO + off, W4lo + widx);
        }
        cp_commit();
    };

    float acc[2][8][4];
#pragma unroll
    for (int mi = 0; mi < 2; mi++)
#pragma unroll
        for (int nb = 0; nb < 8; nb++)
#pragma unroll
            for (int q = 0; q < 4; q++) acc[mi][nb][q] = 0.f;

    int g  = lane >> 3;
    int ri = lane & 7;

    prefetch(0, 0);

    for (int c = 0; c < CH; ++c) {
        if (c + 1 < CH) {
            prefetch(c + 1, (c + 1) & 1);
            cp_wait<1>();
        } else {
            cp_wait<0>();
        }
        __syncthreads();

        uint32_t st = sb + (c & 1) * ST_STRIDE;

#pragma unroll
        for (int ks = 0; ks < 4; ++ks) {
            uint32_t a_hi[2][4], a_lo[2][4];
#pragma unroll
            for (int mi = 0; mi < 2; ++mi) {
                int row = warp_m * 32 + mi * 16 + ((g & 1) << 3) + ri;
                int kb  = ks * 32 + ((g >> 1) << 4);
                uint32_t off = SMEM_SWIZZLE_128B((uint32_t)(row * 128 + kb));
                ldsm_x4(a_hi[mi], st + ST_AHI + off);
                ldsm_x4(a_lo[mi], st + ST_ALO + off);
            }
#pragma unroll
            for (int p = 0; p < 3; ++p) {
                uint32_t woff = (p == 1) ? ST_WLO : ST_WHI;
                uint32_t (*af)[4] = (p == 2) ? a_lo : a_hi;
                uint32_t b[8][2];
#pragma unroll
                for (int nb2 = 0; nb2 < 4; ++nb2) {
                    int row = warp_n * 64 + nb2 * 16 + ((g >> 1) << 3) + ri;
                    int kb  = ks * 32 + ((g & 1) << 4);
                    uint32_t off = SMEM_SWIZZLE_128B((uint32_t)(row * 128 + kb));
                    uint32_t r[4];
                    ldsm_x4(r, st + woff + off);
                    b[nb2 * 2 + 0][0] = r[0];
                    b[nb2 * 2 + 0][1] = r[1];
                    b[nb2 * 2 + 1][0] = r[2];
                    b[nb2 * 2 + 1][1] = r[3];
                }
#pragma unroll
                for (int mi = 0; mi < 2; ++mi)
#pragma unroll
                    for (int nb = 0; nb < 8; ++nb)
                        mma_bf16(acc[mi][nb], af[mi], b[nb]);
            }
        }
        __syncthreads();
    }

    const float* bias_s = (const float*)(smem + SM_BIAS_OFF);
    int qrow = lane >> 2;
    int qcol = (lane & 3) * 2;
#pragma unroll
    for (int mi = 0; mi < 2; ++mi) {
#pragma unroll
        for (int nb = 0; nb < 8; ++nb) {
            int col = warp_n * 64 + nb * 8 + qcol;
            float b0 = bias_s[col], b1 = bias_s[col + 1];
            int r0 = base + warp_m * 32 + mi * 16 + qrow;
            if (r0 < NN) {
                float2 v0 = make_float2(acc[mi][nb][0] + b0, acc[mi][nb][1] + b1);
                *(float2*)(out + (size_t)r0 * DD + col) = v0;
            }
            int r1 = r0 + 8;
            if (r1 < NN) {
                float2 v1 = make_float2(acc[mi][nb][2] + b0, acc[mi][nb][3] + b1);
                *(float2*)(out + (size_t)r1 * DD + col) = v1;
            }
        }
    }
}

__global__ __launch_bounds__(256)
void gemm_fused_kernel(const float* __restrict__ lin_b,
                       const float* __restrict__ conv_b) {
    extern __shared__ char smem[];
    uint32_t sb = smem_to_u32(smem);
    if (blockIdx.x < G1_BLOCKS) {
        gemm_body<128>(blockIdx.x, smem, sb, g_A1hi, g_A1lo, g_W1hi, g_W1lo,
                       g_transformed, lin_b);
    } else {
        gemm_body<384>(blockIdx.x - G1_BLOCKS, smem, sb, g_A2hi, g_A2lo,
                       g_W2hi, g_W2lo, g_conv, conv_b);
    }
}

// ---------------- K7: gather-sum + mean + conv add + expmap0 ----------------
__global__ void finalize_kernel(const float* __restrict__ curv,
                                float* __restrict__ out) {
    int n = (blockIdx.x * blockDim.x + threadIdx.x) >> 5;
    int lane = threadIdx.x & 31;
    if (n >= NN) return;

    int s = g_rowstart[n];
    int e = g_rowstart[n + 1];
    const float4* T = (const float4*)g_transformed;

    float4 a = make_float4(0.f, 0.f, 0.f, 0.f);
    int p = s;
    for (; p + 4 <= e; p += 4) {
        int i0 = g_csr[p + 0], i1 = g_csr[p + 1];
        int i2 = g_csr[p + 2], i3 = g_csr[p + 3];
        float4 v0 = T[i0 * 32 + lane];
        float4 v1 = T[i1 * 32 + lane];
        float4 v2 = T[i2 * 32 + lane];
        float4 v3 = T[i3 * 32 + lane];
        a.x += (v0.x + v1.x) + (v2.x + v3.x);
        a.y += (v0.y + v1.y) + (v2.y + v3.y);
        a.z += (v0.z + v1.z) + (v2.z + v3.z);
        a.w += (v0.w + v1.w) + (v2.w + v3.w);
    }
    for (; p < e; ++p) {
        int i0 = g_csr[p];
        float4 v0 = T[i0 * 32 + lane];
        a.x += v0.x; a.y += v0.y; a.z += v0.z; a.w += v0.w;
    }

    float inv = (e > s) ? 1.0f / (float)(e - s) : 0.0f;
    float4 cv = ((const float4*)g_conv)[n * 32 + lane];
    float4 v = make_float4(cv.x + a.x * inv, cv.y + a.y * inv,
                           cv.z + a.z * inv, cv.w + a.w * inv);

    float ss = v.x * v.x + v.y * v.y + v.z * v.z + v.w * v.w;
#pragma unroll
    for (int off = 16; off; off >>= 1) ss += __shfl_xor_sync(0xffffffffu, ss, off);

    float c  = fabsf(curv[0]);
    float sc = sqrtf(c);
    float un = fmaxf(sqrtf(ss), 1e-15f);
    float arg = sc * un;
    float f = tanhf(arg) / arg;

    ((float4*)out)[n * 32 + lane] =
        make_float4(v.x * f, v.y * f, v.z * f, v.w * f);
}

// ---------------- launch ----------------------------------------------------
extern "C" void kernel_launch(void* const* d_in, const int* in_sizes, int n_in,
                              void* d_out, int out_size) {
    const float* node   = (const float*)d_in[0];
    const float* h1     = (const float*)d_in[1];
    const float* h2     = (const float*)d_in[2];
    const float* h3     = (const float*)d_in[3];
    const float* lin_w  = (const float*)d_in[4];
    const float* lin_b  = (const float*)d_in[5];
    const float* conv_w = (const float*)d_in[6];
    const float* conv_b = (const float*)d_in[7];
    const float* curv   = (const float*)d_in[8];
    const int*   esrc   = (const int*)d_in[9];
    const int*   edst   = (const int*)d_in[10];
    float* out = (float*)d_out;

    cudaFuncSetAttribute(gemm_fused_kernel,
                         cudaFuncAttributeMaxDynamicSharedMemorySize, SM_GEMM_TOTAL);

    prep_kernel<<<(DD * DD + 3 * DD * DD + 255) / 256, 256>>>(lin_w, conv_w);
    tangent_deg_kernel<<<DEG_BLOCKS + TAN_BLOCKS, 256>>>(node, h1, h2, h3, curv, edst);
    scan12_kernel<<<SCAN_BLOCKS, 1024>>>();
    scan3_kernel<<<SCAN_BLOCKS, 1024>>>();
    place_kernel<<<(EE + 255) / 256, 256>>>(esrc, edst);
    gemm_fused_kernel<<<G1_BLOCKS + (NN + 127) / 128, 256, SM_GEMM_TOTAL>>>(lin_b, conv_b);
    finalize_kernel<<<(NN + 7) / 8, 256>>>(curv, out);
}